// round 17
// baseline (speedup 1.0000x reference)
#include <cuda_runtime.h>
#include <math.h>

#define B_  32
#define T_  64
#define KU_ 512
#define H_  90
#define H2_ 45               // H/2
#define H3_ 270
#define NR  (B_*KU_)         // 16384
#define RPC 16               // rows per CTA (main)
#define NCTA (NR/RPC)        // 1024
#define SL_ 16               // prep slices per batch
#define KS_ (KU_/SL_)        // 32 k's per slice

// Persistent scratch (zero runtime allocation). Ping-pong states.
__device__ float g_states[2][NR*H_];
__device__ float g_gi0[H3_];        // gi for inactive rows
__device__ float g_sync[NR*H_];     // sync rows (valid only where nb!=0 this step)
__device__ float g_prop[B_*H_];     // prop_inf per batch (written by sl==0)
__device__ float g_rflp[B_][SL_][H_]; // partial reflec sums per k-slice
__device__ float g_gia[(size_t)NR*H3_]; // gi for active rows

__device__ __forceinline__ float sigf(float x){ return 1.0f/(1.0f+__expf(-x)); }
__device__ __forceinline__ float tanhfast(float x){ return 2.0f*sigf(2.0f*x) - 1.0f; }

__device__ __forceinline__ unsigned long long pack2(float a, float b){
    unsigned long long r;
    asm("mov.b64 %0, {%1, %2};" : "=l"(r) : "f"(a), "f"(b));
    return r;
}
__device__ __forceinline__ void unpack2(unsigned long long v, float& a, float& b){
    asm("mov.b64 {%0, %1}, %2;" : "=f"(a), "=f"(b) : "l"(v));
}
// Packed dual fp32 FMA (sm_100+)
__device__ __forceinline__ void ffma2(unsigned long long& acc,
                                      unsigned long long a, unsigned long long b){
    asm("fma.rn.f32x2 %0, %1, %2, %0;" : "+l"(acc) : "l"(a), "l"(b));
}

// ---------------------------------------------------------------------------
__global__ void k_zero()
{
    float* p = (float*)g_states;
    int n = 2*NR*H_;
    for (int i = blockIdx.x*blockDim.x + threadIdx.x; i < n; i += gridDim.x*blockDim.x)
        p[i] = 0.0f;
}

__global__ void k_gi0(const float* __restrict__ bag,
                      const float* __restrict__ WiR,
                      const float* __restrict__ biR)
{
    __shared__ float inf0[H_];
    int tid = threadIdx.x;
    if (tid < H_) inf0[tid] = fmaxf(bag[tid], 0.0f);
    __syncthreads();
    if (tid < H3_) {
        float v = biR[tid];
        #pragma unroll 6
        for (int i = 0; i < H_; i++) v += inf0[i] * WiR[i*H3_ + tid];
        g_gi0[tid] = v;
    }
}

__global__ void k_copyout(float* __restrict__ out)
{
    int n = NR*H_;
    for (int i = blockIdx.x*blockDim.x + threadIdx.x; i < n; i += gridDim.x*blockDim.x)
        out[i] = g_states[0][i];
}

// ---------------------------------------------------------------------------
// Prep1: next_self GRU, sync rows + reflec partials, AND gi for active k!=q
// rows (slice-local). grid = (32 batches, 16 slices of 32 k), block 288.
__global__ void __launch_bounds__(288) k_prep1(int t,
    const int*   __restrict__ qs,   const int*   __restrict__ as_,
    const float* __restrict__ resp, const float* __restrict__ ce,
    const float* __restrict__ nb,   const float* __restrict__ succ,
    const float* __restrict__ WiS,  const float* __restrict__ WhS,
    const float* __restrict__ biS,  const float* __restrict__ bhS,
    const float* __restrict__ Wsy,  const float* __restrict__ bsy,
    const float* __restrict__ Wpr,  const float* __restrict__ bpr,
    const float* __restrict__ Wag,  const float* __restrict__ bag,
    const float* __restrict__ WiR,  const float* __restrict__ biR)
{
    const float* __restrict__ Sp = g_states[t & 1];
    int b = blockIdx.x, sl = blockIdx.y, tid = threadIdx.x;

    __shared__ float sSelf[H_], sX[H_], sGi[H3_], sGh[H3_], sNs[H_], sNsDot[H_];
    __shared__ float sProp[H_], sComb[H_], sInf[H_];
    __shared__ float sNb[KS_], sSc[KS_];
    __shared__ int   sFlags[2];

    int q = qs[b*T_ + t];
    int a = as_[b*T_ + t];
    if (tid < KS_) {
        sNb[tid] = nb[q*KU_ + sl*KS_ + tid];
        sSc[tid] = succ[q*KU_ + sl*KS_ + tid];
    }
    if (tid < H_) { sSelf[tid] = Sp[(b*KU_ + q)*H_ + tid]; sX[tid] = resp[a*H_ + tid]; }
    __syncthreads();

    if (tid == 0) {
        int anyNv = 0, anyScO = 0;
        for (int kk = 0; kk < KS_; kk++) {
            if (sNb[kk] != 0.0f) anyNv = 1;
            if (sSc[kk] != 0.0f && (sl*KS_ + kk) != q) anyScO = 1;
        }
        sFlags[0] = anyNv; sFlags[1] = anyScO;
    }
    __syncthreads();
    int anyNv = sFlags[0], anyScO = sFlags[1];

    if (!anyNv && !anyScO && sl != 0) {       // empty slice: zero partial, exit
        if (tid < H_) g_rflp[b][sl][tid] = 0.0f;
        return;
    }

    // next_self GRU (redundant per slice; needed for nsdot/prop)
    if (tid < H3_) {
        float gi = biS[tid], gh = bhS[tid];
        #pragma unroll 6
        for (int i = 0; i < H_; i++) {
            gi += sX[i]    * WiS[i*H3_ + tid];
            gh += sSelf[i] * WhS[i*H3_ + tid];
        }
        sGi[tid] = gi; sGh[tid] = gh;
    }
    __syncthreads();
    if (tid < H_) {
        float r = sigf(sGi[tid]       + sGh[tid]);
        float z = sigf(sGi[H_+tid]    + sGh[H_+tid]);
        float g = tanhfast(sGi[2*H_+tid] + r*sGh[2*H_+tid]);
        sNs[tid] = (1.0f - z)*g + z*sSelf[tid];
    }
    __syncthreads();
    if (tid < H_) {
        if (anyNv) {
            float nd = 0.0f;
            #pragma unroll 6
            for (int i = 0; i < H_; i++) nd += sNs[i] * Wsy[(H_+i)*H_ + tid];
            sNsDot[tid] = nd;
        }
        if (anyScO || sl == 0) {
            float p = bpr[tid];
            #pragma unroll 6
            for (int i = 0; i < H_; i++) p += (sNs[i] - sSelf[i]) * Wpr[i*H_ + tid];
            #pragma unroll 6
            for (int i = 0; i < H_; i++) p += ce[q*H_ + i] * Wpr[(H_+i)*H_ + tid];
            p = fmaxf(p, 0.0f);
            sProp[tid] = p;
            if (sl == 0) g_prop[b*H_ + tid] = p;
        }
    }
    __syncthreads();

    // Per-k: sync value (nv!=0), then gi for active k!=q rows (val stays in regs)
    float rfl = 0.0f;
    for (int kk = 0; kk < KS_; kk++) {
        int k = sl*KS_ + kk;
        float nv = sNb[kk], sc = sSc[kk];
        float val = 0.0f;
        if (nv != 0.0f) {                       // block-uniform
            if (tid < H_) {
                float v = bsy[tid] + sNsDot[tid];
                const float* hr = Sp + (b*KU_ + k)*H_;
                const float* cr = ce + k*H_;
                #pragma unroll 6
                for (int i = 0; i < H_; i++) v += hr[i] * Wsy[i*H_ + tid];
                #pragma unroll 6
                for (int i = 0; i < H_; i++) v += cr[i] * Wsy[(2*H_+i)*H_ + tid];
                val = nv * fmaxf(v, 0.0f);
                g_sync[(b*KU_ + k)*H_ + tid] = val;   // q row read by prep2q
                rfl += val;
            }
        }
        bool actO = (k != q) && (nv != 0.0f || sc != 0.0f);   // block-uniform
        if (actO) {
            if (tid < H_)
                sComb[tid] = 0.5f*val + ((sc != 0.0f) ? 0.5f*sc*sProp[tid] : 0.0f);
            __syncthreads();
            if (tid < H_) {
                float v = bag[tid];
                #pragma unroll 6
                for (int i = 0; i < H_; i++) v += sComb[i] * Wag[i*H_ + tid];
                sInf[tid] = fmaxf(v, 0.0f);
            }
            __syncthreads();
            if (tid < H3_) {
                float v = biR[tid];
                #pragma unroll 6
                for (int i = 0; i < H_; i++) v += sInf[i] * WiR[i*H3_ + tid];
                g_gia[(size_t)(b*KU_ + k)*H3_ + tid] = v;
            }
            __syncthreads();
        }
    }
    if (tid < H_) g_rflp[b][sl][tid] = rfl;
}

// ---------------------------------------------------------------------------
// Prep2q: ONLY the k==q row per batch (needs cross-slice reflec). grid = 32.
__global__ void __launch_bounds__(288) k_prep2q(int t,
    const int*   __restrict__ qs,
    const float* __restrict__ nb,  const float* __restrict__ succ,
    const float* __restrict__ Wag, const float* __restrict__ bag,
    const float* __restrict__ WiR, const float* __restrict__ biR)
{
    int b = blockIdx.x, tid = threadIdx.x;
    __shared__ float sComb[H_], sInf[H_];

    int q = qs[b*T_ + t];
    int row = b*KU_ + q;
    if (tid < H_) {
        float ref = 0.0f;
        #pragma unroll
        for (int s = 0; s < SL_; s++) ref += g_rflp[b][s][tid];
        float nv = nb[q*KU_ + q];
        float sv = (nv != 0.0f) ? g_sync[row*H_ + tid] : 0.0f;
        sv += ref;
        float sc = succ[q*KU_ + q];
        sComb[tid] = 0.5f*sv + ((sc != 0.0f) ? 0.5f*sc*g_prop[b*H_ + tid] : 0.0f);
    }
    __syncthreads();
    if (tid < H_) {
        float v = bag[tid];
        #pragma unroll 6
        for (int i = 0; i < H_; i++) v += sComb[i] * Wag[i*H_ + tid];
        sInf[tid] = fmaxf(v, 0.0f);
    }
    __syncthreads();
    if (tid < H3_) {
        float v = biR[tid];
        #pragma unroll 6
        for (int i = 0; i < H_; i++) v += sInf[i] * WiR[i*H3_ + tid];
        g_gia[(size_t)row*H3_ + tid] = v;
    }
}

// ---------------------------------------------------------------------------
// Main: recurrent gh GEMM (f32x2 packed, 16 rows/CTA) + gates + out.
// grid = 1024, block 288, 4 CTAs/SM.
__global__ void __launch_bounds__(288, 4) k_main(int t,
    const int*   __restrict__ qs,
    const float* __restrict__ nb,   const float* __restrict__ succ,
    const float* __restrict__ WhR,  const float* __restrict__ bhR,
    const float* __restrict__ Wo,   const float* __restrict__ bo,
    float* __restrict__ out)
{
    const float* __restrict__ Sp = g_states[t & 1];
    float*       __restrict__ Sn = g_states[(t + 1) & 1];

    int tid   = threadIdx.x;
    int b     = blockIdx.x >> 5;
    int kbase = (blockIdx.x & 31) * RPC;
    int rb    = b*KU_ + kbase;

    __shared__ __align__(16) float4 sP[H2_][8];
    __shared__ float sGH[RPC][H3_];
    __shared__ float sWo[H_];
    __shared__ int   sAct[RPC];

    int q = qs[b*T_ + t];

    if (tid < H_) sWo[tid] = Wo[tid];
    if (tid < RPC) {
        int k = kbase + tid;
        sAct[tid] = (k == q || nb[q*KU_ + k] != 0.0f || succ[q*KU_ + k] != 0.0f) ? 1 : 0;
    }
    for (int idx = tid; idx < H2_*8; idx += 288) {
        int i2 = idx >> 3, p = idx & 7;
        const float* ra = Sp + (rb + 2*p    )*H_ + 2*i2;
        const float* rbp= Sp + (rb + 2*p + 1)*H_ + 2*i2;
        float2 va = *(const float2*)ra;
        float2 vb = *(const float2*)rbp;
        sP[i2][p] = make_float4(va.x, vb.x, va.y, vb.y);
    }
    __syncthreads();

    if (tid < H3_) {
        int j = tid;
        float bh = bhR[j];
        unsigned long long acc[8];
        unsigned long long bh2 = pack2(bh, bh);
        #pragma unroll
        for (int p = 0; p < 8; p++) acc[p] = bh2;
        #pragma unroll 5
        for (int i2 = 0; i2 < H2_; i2++) {
            float wa = __ldg(WhR + (2*i2    )*H3_ + j);
            float wb = __ldg(WhR + (2*i2 + 1)*H3_ + j);
            unsigned long long w2a = pack2(wa, wa);
            unsigned long long w2b = pack2(wb, wb);
            #pragma unroll
            for (int p = 0; p < 8; p++) {
                ulonglong2 uu = *(const ulonglong2*)&sP[i2][p];
                ffma2(acc[p], w2a, uu.x);
                ffma2(acc[p], w2b, uu.y);
            }
        }
        #pragma unroll
        for (int p = 0; p < 8; p++) {
            float lo, hi; unpack2(acc[p], lo, hi);
            sGH[2*p][j] = lo; sGH[2*p+1][j] = hi;
        }
    }
    __syncthreads();

    float* sNH = (float*)sP;   // sP dead after GEMM
    for (int w = tid; w < RPC*H_; w += 288) {
        int r = w / H_, jj = w - r*H_;
        int row = rb + r;
        const float* gi = sAct[r] ? (g_gia + (size_t)row*H3_) : g_gi0;
        float g0 = __ldg(gi + jj);
        float g1 = __ldg(gi + H_ + jj);
        float g2 = __ldg(gi + 2*H_ + jj);
        float gr = sigf(g0 + sGH[r][jj]);
        float gz = sigf(g1 + sGH[r][H_+jj]);
        float gg = tanhfast(g2 + gr*sGH[r][2*H_+jj]);
        float nh = (1.0f - gz)*gg + gz*Sp[row*H_ + jj];
        Sn[row*H_ + jj] = nh;
        sNH[w] = nh;
    }
    __syncthreads();

    {
        int lane = tid & 31;
        for (int r = tid >> 5; r < RPC; r += 9) {
            float p = 0.0f;
            for (int i = lane; i < H_; i += 32) p += sNH[r*H_ + i] * sWo[i];
            #pragma unroll
            for (int o = 16; o > 0; o >>= 1) p += __shfl_down_sync(0xffffffffu, p, o);
            if (lane == 0) out[(size_t)t*NR + rb + r] = sigf(p + bo[0]);
        }
    }
}

// ---------------------------------------------------------------------------
extern "C" void kernel_launch(void* const* d_in, const int* in_sizes, int n_in,
                              void* d_out, int out_size)
{
    const int*   qs   = (const int*)  d_in[0];
    const int*   as_  = (const int*)  d_in[1];
    const float* resp = (const float*)d_in[2];
    const float* ce   = (const float*)d_in[3];
    const float* nb   = (const float*)d_in[4];
    const float* succ = (const float*)d_in[5];
    const float* WiS  = (const float*)d_in[6];
    const float* WhS  = (const float*)d_in[7];
    const float* biS  = (const float*)d_in[8];
    const float* bhS  = (const float*)d_in[9];
    const float* WiR  = (const float*)d_in[10];
    const float* WhR  = (const float*)d_in[11];
    const float* biR  = (const float*)d_in[12];
    const float* bhR  = (const float*)d_in[13];
    const float* Wsy  = (const float*)d_in[14];
    const float* bsy  = (const float*)d_in[15];
    const float* Wpr  = (const float*)d_in[16];
    const float* bpr  = (const float*)d_in[17];
    const float* Wag  = (const float*)d_in[18];
    const float* bag  = (const float*)d_in[19];
    const float* Wo   = (const float*)d_in[20];
    const float* bo   = (const float*)d_in[21];
    float* out = (float*)d_out;

    k_zero<<<256, 256>>>();
    k_gi0<<<1, 288>>>(bag, WiR, biR);
    for (int t = 0; t < T_; t++) {
        k_prep1<<<dim3(B_, SL_), 288>>>(t, qs, as_, resp, ce, nb, succ,
                                        WiS, WhS, biS, bhS, Wsy, bsy, Wpr, bpr,
                                        Wag, bag, WiR, biR);
        k_prep2q<<<B_, 288>>>(t, qs, nb, succ, Wag, bag, WiR, biR);
        k_main<<<NCTA, 288>>>(t, qs, nb, succ, WhR, bhR, Wo, bo, out);
    }
    // T=64 even -> final states in buffer 0; append after outputs.
    k_copyout<<<512, 256>>>(out + (size_t)T_*NR);
}